// round 16
// baseline (speedup 1.0000x reference)
#include <cuda_runtime.h>
#include <cuda_bf16.h>
#include <cuda_fp16.h>
#include <math.h>
#include <stdint.h>

#define NB 16
#define NCDD 5
#define NHIS 50
#define NS 20
#define NT 41
#define NE 300
#define NF 256
#define NH 16
#define NDV 16
#define NQD 200
#define NSEQ 4000
#define NUROWS 21600
#define MID_BASE 17600
#define MVAL 164000
#define SCALE_F 0.057735026918962576f
#define CONV_K 928

#define CP_ASYNC16(dst, src) \
    asm volatile("cp.async.cg.shared.global [%0], [%1], 16;" :: "r"(dst), "l"(src))
#define CP_COMMIT() asm volatile("cp.async.commit_group;" ::: "memory")
#define CP_WAIT0() asm volatile("cp.async.wait_group 0;" ::: "memory")

// -------- static device scratch (no allocations) --------
__device__ half g_xub[NUROWS * NF];
__device__ half g_WcatTb[4352 * 256];
__device__ float g_bcat[4352];
__device__ half g_WkTb[200 * 256];
__device__ half g_cwb[256 * CONV_K];
__device__ half g_qb[(size_t)NUROWS * 4096];
__device__ float g_xv[(size_t)NUROWS * 256];
__device__ half g_valb[(size_t)MVAL * NF];
__device__ float g_spart[(size_t)MVAL * 8];
__device__ float g_rep[(size_t)NSEQ * NF];

// -------- kernel 0: pack transposed fp16 weights + bias --------
__global__ void prep_kernel(const float* __restrict__ Wq, const float* __restrict__ bq,
                            const float* __restrict__ Wv, const float* __restrict__ bv,
                            const float* __restrict__ Wk, const float* __restrict__ cw) {
    int idx = blockIdx.x * 256 + threadIdx.x;
    if (idx < 4352 * 256) {
        int nn = idx >> 8, k = idx & 255;
        float w;
        if (nn < 4096) {
            int h = nn >> 8, g = nn & 255;
            w = Wq[(h * 256 + k) * 256 + g];
        } else {
            int jj = nn - 4096;
            int h = jj >> 4, d = jj & 15;
            w = Wv[(h * 256 + k) * 16 + d];
        }
        g_WcatTb[idx] = __float2half(w);
    }
    if (idx < 200 * 256) {
        int nn = idx >> 8, k = idx & 255;
        g_WkTb[idx] = __float2half(Wk[k * 200 + nn]);
    }
    if (idx < 256 * CONV_K) {
        int f = idx / CONV_K, k = idx - f * CONV_K;
        g_cwb[idx] = __float2half(k < 900 ? cw[k * 256 + f] : 0.f);
    }
    if (idx < 4352) {
        if (idx < 4096) {
            int h = idx >> 8, g = idx & 255;
            g_bcat[idx] = bq[h * 256 + g];
        } else {
            g_bcat[idx] = bv[idx - 4096]; // bv folds through softmax (rows sum to 1)
        }
    }
}

// -------- kernel 1: conv as fp16 mma GEMM over im2col rows (fp32 acc: K=928 chain) ----
__global__ void __launch_bounds__(256, 2) conv_mma_kernel(const int* __restrict__ cand,
                                                          const int* __restrict__ clk,
                                                          const float* __restrict__ emb,
                                                          const float* __restrict__ cb) {
    __shared__ half As[128 * 40];
    __shared__ half Bs[128 * 40];
    __shared__ int st[128][3];
    int tid = threadIdx.x;
    int w = tid >> 5, lane = tid & 31;
    int wm = w >> 2, wn = w & 3;
    int m0 = blockIdx.y * 128;
    int n0 = blockIdx.x * 128;

    if (tid < 128) {
        int row = m0 + tid;
        int t0 = -1, t1 = -1, t2 = -1;
        if (row < NUROWS) {
            if (row < 1600) {
                int bc = row / 20, t = row - bc * 20;
                const int* ct = cand + bc * 20;
                t0 = (t - 1 >= 0) ? ct[t - 1] : -1;
                t1 = ct[t];
                t2 = (t + 1 < 20) ? ct[t + 1] : 1;
            } else if (row < MID_BASE) {
                int r2 = row - 1600;
                int bh = r2 / 20, tt = r2 - bh * 20;
                const int* ht = clk + bh * 20;
                t0 = (tt == 0) ? 1 : ht[tt - 1];
                t1 = ht[tt];
                t2 = (tt + 1 < 20) ? ht[tt + 1] : -1;
            } else {
                int nn = row - MID_BASE;
                int b = nn / 250, rr = nn - b * 250;
                int c = rr / 50, hh = rr - c * 50;
                t0 = cand[(b * 5 + c) * 20 + 19];
                t1 = 1;
                t2 = clk[(b * 50 + hh) * 20 + 0];
            }
        }
        st[tid][0] = t0; st[tid][1] = t1; st[tid][2] = t2;
    }

    uint32_t As_u = (uint32_t)__cvta_generic_to_shared(As);
    uint32_t Bs_u = (uint32_t)__cvta_generic_to_shared(Bs);

    float acc[4][4][4];
#pragma unroll
    for (int i = 0; i < 4; ++i)
#pragma unroll
        for (int j = 0; j < 4; ++j)
#pragma unroll
            for (int e = 0; e < 4; ++e) acc[i][j][e] = 0.f;

    for (int kc = 0; kc < CONV_K; kc += 32) {
        __syncthreads();
#pragma unroll
        for (int j = 0; j < 4; ++j) {
            int i = tid + j * 256;
            int r = i >> 3, q = i & 7;
            int k0 = kc + q * 4;
            uint2 u = make_uint2(0, 0);
            if (k0 < 900) {
                int tap = k0 / 300;
                int e0 = k0 - tap * 300;
                int tok = st[r][tap];
                if (tok >= 0) {
                    float4 v = *(const float4*)(emb + (size_t)tok * 300 + e0);
                    __half2 p0 = __floats2half2_rn(v.x, v.y);
                    __half2 p1 = __floats2half2_rn(v.z, v.w);
                    u.x = *(uint32_t*)&p0;
                    u.y = *(uint32_t*)&p1;
                }
            }
            *(uint2*)(As + r * 40 + q * 4) = u;
        }
#pragma unroll
        for (int j = 0; j < 2; ++j) {
            int i = tid + j * 256;
            int r = i >> 2, kq = i & 3;
            *(uint4*)(Bs + r * 40 + kq * 8) =
                *(const uint4*)(g_cwb + (size_t)(n0 + r) * CONV_K + kc + kq * 8);
        }
        __syncthreads();
#pragma unroll
        for (int ks = 0; ks < 2; ++ks) {
            uint32_t a[4][4], b[4][2];
#pragma unroll
            for (int i = 0; i < 4; ++i) {
                uint32_t addr = As_u +
                    (uint32_t)(((wm * 64 + i * 16 + (lane & 15)) * 40 + ks * 16 + (lane >> 4) * 8) * 2);
                asm volatile("ldmatrix.sync.aligned.m8n8.x4.shared.b16 {%0,%1,%2,%3}, [%4];"
                    : "=r"(a[i][0]), "=r"(a[i][1]), "=r"(a[i][2]), "=r"(a[i][3]) : "r"(addr));
            }
#pragma unroll
            for (int j = 0; j < 4; ++j) {
                int nr = wn * 32 + j * 8 + (lane & 7);
                uint32_t addr = Bs_u +
                    (uint32_t)((nr * 40 + ks * 16 + ((lane >> 3) & 1) * 8) * 2);
                asm volatile("ldmatrix.sync.aligned.m8n8.x2.shared.b16 {%0,%1}, [%2];"
                    : "=r"(b[j][0]), "=r"(b[j][1]) : "r"(addr));
            }
#pragma unroll
            for (int i = 0; i < 4; ++i)
#pragma unroll
                for (int j = 0; j < 4; ++j)
                    asm volatile(
                        "mma.sync.aligned.m16n8k16.row.col.f32.f16.f16.f32 "
                        "{%0,%1,%2,%3}, {%4,%5,%6,%7}, {%8,%9}, {%0,%1,%2,%3};"
                        : "+f"(acc[i][j][0]), "+f"(acc[i][j][1]),
                          "+f"(acc[i][j][2]), "+f"(acc[i][j][3])
                        : "r"(a[i][0]), "r"(a[i][1]), "r"(a[i][2]), "r"(a[i][3]),
                          "r"(b[j][0]), "r"(b[j][1]));
        }
    }

    int gid = lane >> 2;
#pragma unroll
    for (int i = 0; i < 4; ++i) {
#pragma unroll
        for (int j = 0; j < 4; ++j) {
            int c0 = n0 + wn * 32 + j * 8 + (lane & 3) * 2;
            float b0 = cb[c0], b1 = cb[c0 + 1];
#pragma unroll
            for (int hf = 0; hf < 2; ++hf) {
                int m = m0 + wm * 64 + i * 16 + gid + hf * 8;
                if (m >= NUROWS) continue;
                float v0 = fmaxf(acc[i][j][hf * 2 + 0] + b0, 0.f);
                float v1 = fmaxf(acc[i][j][hf * 2 + 1] + b1, 0.f);
                __half2 p = __floats2half2_rn(v0, v1);
                *(uint32_t*)(g_xub + (size_t)m * 256 + c0) = *(uint32_t*)&p;
            }
        }
    }
}

// -------- fp16 tensor-core GEMM (fp16 ACCUMULATE), K=256, double-buffered --------
// MODE 0: n<4096 -> g_qb fp16; n>=4096 -> g_xv fp32.
// MODE 1: fused word-k partials -> g_spart.
template <int MODE>
__global__ void __launch_bounds__(256, 2) gemm_mma_kernel(const half* __restrict__ Ag,
                                                          const half* __restrict__ Bt,
                                                          const float* __restrict__ bias,
                                                          const float* __restrict__ qw,
                                                          int M, int N) {
    __shared__ half As[128 * 56];
    __shared__ half Bs[128 * 56];
    __shared__ float qws[200];
    int tid = threadIdx.x;
    int w = tid >> 5, lane = tid & 31;
    int wm = w >> 2, wn = w & 3;
    int m0 = blockIdx.y * 128;
    int n0 = blockIdx.x * 128;

    if (MODE == 1 && tid < 200) qws[tid] = qw[tid];

    uint32_t As_u = (uint32_t)__cvta_generic_to_shared(As);
    uint32_t Bs_u = (uint32_t)__cvta_generic_to_shared(Bs);

    // fp16 accumulators: [i][j][0]={rows gid: c0,c1}, [1]={rows gid+8: c0,c1}
    uint32_t acc[4][4][2];
#pragma unroll
    for (int i = 0; i < 4; ++i)
#pragma unroll
        for (int j = 0; j < 4; ++j) { acc[i][j][0] = 0u; acc[i][j][1] = 0u; }

    uint4 pre[4];
#pragma unroll
    for (int j = 0; j < 4; ++j) {
        int i = tid + j * 256;
        int r = (i >> 2) & 127;
        int kq = i & 3;
        uint4 v = make_uint4(0, 0, 0, 0);
        if (i < 512) {
            int m = m0 + r;
            if (m < M) v = *(const uint4*)(Ag + (size_t)m * 256 + kq * 8);
        } else {
            int nn = n0 + r;
            if (nn < N) v = *(const uint4*)(Bt + (size_t)nn * 256 + kq * 8);
        }
        pre[j] = v;
    }

    for (int kc = 0; kc < 256; kc += 32) {
        __syncthreads();
#pragma unroll
        for (int j = 0; j < 4; ++j) {
            int i = tid + j * 256;
            int r = (i >> 2) & 127;
            int kq = i & 3;
            if (i < 512) *(uint4*)(As + r * 56 + kq * 8) = pre[j];
            else         *(uint4*)(Bs + r * 56 + kq * 8) = pre[j];
        }
        __syncthreads();
        if (kc + 32 < 256) {
            int kn = kc + 32;
#pragma unroll
            for (int j = 0; j < 4; ++j) {
                int i = tid + j * 256;
                int r = (i >> 2) & 127;
                int kq = i & 3;
                uint4 v = make_uint4(0, 0, 0, 0);
                if (i < 512) {
                    int m = m0 + r;
                    if (m < M) v = *(const uint4*)(Ag + (size_t)m * 256 + kn + kq * 8);
                } else {
                    int nn = n0 + r;
                    if (nn < N) v = *(const uint4*)(Bt + (size_t)nn * 256 + kn + kq * 8);
                }
                pre[j] = v;
            }
        }
#pragma unroll
        for (int ks = 0; ks < 2; ++ks) {
            uint32_t a[4][4], b[4][2];
#pragma unroll
            for (int i = 0; i < 4; ++i) {
                uint32_t addr = As_u +
                    (uint32_t)(((wm * 64 + i * 16 + (lane & 15)) * 56 + ks * 16 + (lane >> 4) * 8) * 2);
                asm volatile("ldmatrix.sync.aligned.m8n8.x4.shared.b16 {%0,%1,%2,%3}, [%4];"
                    : "=r"(a[i][0]), "=r"(a[i][1]), "=r"(a[i][2]), "=r"(a[i][3]) : "r"(addr));
            }
#pragma unroll
            for (int j = 0; j < 4; ++j) {
                int nr = wn * 32 + j * 8 + (lane & 7);
                uint32_t addr = Bs_u +
                    (uint32_t)((nr * 56 + ks * 16 + ((lane >> 3) & 1) * 8) * 2);
                asm volatile("ldmatrix.sync.aligned.m8n8.x2.shared.b16 {%0,%1}, [%2];"
                    : "=r"(b[j][0]), "=r"(b[j][1]) : "r"(addr));
            }
#pragma unroll
            for (int i = 0; i < 4; ++i)
#pragma unroll
                for (int j = 0; j < 4; ++j)
                    asm volatile(
                        "mma.sync.aligned.m16n8k16.row.col.f16.f16.f16.f16 "
                        "{%0,%1}, {%2,%3,%4,%5}, {%6,%7}, {%0,%1};"
                        : "+r"(acc[i][j][0]), "+r"(acc[i][j][1])
                        : "r"(a[i][0]), "r"(a[i][1]), "r"(a[i][2]), "r"(a[i][3]),
                          "r"(b[j][0]), "r"(b[j][1]));
        }
    }

    int gid = lane >> 2;
    if (MODE == 0) {
#pragma unroll
        for (int i = 0; i < 4; ++i) {
#pragma unroll
            for (int j = 0; j < 4; ++j) {
                int c0 = n0 + wn * 32 + j * 8 + (lane & 3) * 2;
                float b0 = bias[c0], b1 = bias[c0 + 1];
                float2 f0 = __half22float2(*(__half2*)&acc[i][j][0]);
                float2 f1 = __half22float2(*(__half2*)&acc[i][j][1]);
#pragma unroll
                for (int hf = 0; hf < 2; ++hf) {
                    int m = m0 + wm * 64 + i * 16 + gid + hf * 8;
                    if (m >= M) continue;
                    float v0 = (hf ? f1.x : f0.x) + b0;
                    float v1 = (hf ? f1.y : f0.y) + b1;
                    if (c0 < 4096) {
                        __half2 p = __floats2half2_rn(v0, v1);
                        *(uint32_t*)(g_qb + (size_t)m * 4096 + c0) = *(uint32_t*)&p;
                    } else {
                        *(float2*)(g_xv + (size_t)m * 256 + (c0 - 4096)) =
                            make_float2(v0, v1);
                    }
                }
            }
        }
    } else {
        int t4 = lane & 3;
#pragma unroll
        for (int hf = 0; hf < 2; ++hf) {
#pragma unroll
            for (int i = 0; i < 4; ++i) {
                int m = m0 + wm * 64 + i * 16 + gid + hf * 8;
                float part = 0.f;
#pragma unroll
                for (int j = 0; j < 4; ++j) {
                    int c0 = n0 + wn * 32 + j * 8 + t4 * 2;
                    float2 f = __half22float2(*(__half2*)&acc[i][j][hf]);
                    if (c0 < N)
                        part += tanhf(f.x + bias[c0]) * qws[c0];
                    if (c0 + 1 < N)
                        part += tanhf(f.y + bias[c0 + 1]) * qws[c0 + 1];
                }
                part += __shfl_xor_sync(0xffffffffu, part, 1);
                part += __shfl_xor_sync(0xffffffffu, part, 2);
                if (t4 == 0 && m < M)
                    g_spart[(size_t)m * 8 + (n0 >> 7) * 4 + wn] = part;
            }
        }
    }
}

// -------- kernel 3: attention; 1 warp = 1 head, fp16-acc scores, in-place softmax --------
// smem: xb 48*72*2=6912 | qbA 8x6912=55296 | xvTA 8x1792=14336  => 76544 B
#define ATTN_SMEM_BYTES 76544

__global__ void __launch_bounds__(256, 3) attn_kernel() {
    extern __shared__ char smc[];
    half* xb = (half*)smc;
    half* qbA = (half*)(smc + 6912);
    half* xvTA = (half*)(smc + 6912 + 55296);
    __shared__ int rows[41];

    int n = blockIdx.y;
    int hb = blockIdx.x;
    int tid = threadIdx.x;
    int w = tid >> 5;
    int lane = tid & 31;
    int h = hb * 8 + w;
    int t4 = lane & 3;
    int gid = lane >> 2;

    half* qb = qbA + w * 3456;
    half* xvT = xvTA + w * 896;

    uint32_t xb_u = (uint32_t)__cvta_generic_to_shared(xb);
    uint32_t qb_u = (uint32_t)__cvta_generic_to_shared(qb);
    uint32_t xvT_u = (uint32_t)__cvta_generic_to_shared(xvT);

    if (tid < 41) {
        int b = n / 250, rr = n - b * 250;
        int c = rr / 50, hh = rr - c * 50;
        int t = tid, r;
        if (t < 20)       r = (b * 5 + c) * 20 + t;
        else if (t == 20) r = MID_BASE + n;
        else              r = 1600 + (b * 50 + hh) * 20 + (t - 21);
        rows[t] = r;
    }
    __syncthreads();

    for (int i = lane; i < 240; i += 32) {
        int d = i / 15, s = 41 + i % 15;
        xvT[d * 56 + s] = __float2half(0.f);
    }
    for (int i = lane; i < 164; i += 32) {
        int s = i >> 2, dq = (i & 3) * 4;
        float4 v = *(const float4*)(g_xv + (size_t)rows[s] * 256 + h * 16 + dq);
        xvT[(dq + 0) * 56 + s] = __float2half(v.x);
        xvT[(dq + 1) * 56 + s] = __float2half(v.y);
        xvT[(dq + 2) * 56 + s] = __float2half(v.z);
        xvT[(dq + 3) * 56 + s] = __float2half(v.w);
    }

    uint32_t acc[3][6][2];
#pragma unroll
    for (int i = 0; i < 3; ++i)
#pragma unroll
        for (int j = 0; j < 6; ++j) { acc[i][j][0] = 0u; acc[i][j][1] = 0u; }

    for (int kc = 0; kc < 256; kc += 64) {
        __syncthreads();
        for (int i = tid; i < 328; i += 256) {
            int t = i >> 3, kq = i & 7;
            CP_ASYNC16(xb_u + (uint32_t)(t * 144 + kq * 16),
                       g_xub + (size_t)rows[t] * 256 + kc + kq * 8);
        }
        for (int i = lane; i < 328; i += 32) {
            int t = i >> 3, kq = i & 7;
            CP_ASYNC16(qb_u + (uint32_t)(t * 144 + kq * 16),
                       g_qb + (size_t)rows[t] * 4096 + h * 256 + kc + kq * 8);
        }
        CP_COMMIT();
        CP_WAIT0();
        __syncthreads();
#pragma unroll
        for (int ks = 0; ks < 4; ++ks) {
            uint32_t a[3][4], b[3][4];
#pragma unroll
            for (int i = 0; i < 3; ++i) {
                uint32_t addr = qb_u +
                    (uint32_t)(((i * 16 + (lane & 15)) * 72 + ks * 16 + (lane >> 4) * 8) * 2);
                asm volatile("ldmatrix.sync.aligned.m8n8.x4.shared.b16 {%0,%1,%2,%3}, [%4];"
                    : "=r"(a[i][0]), "=r"(a[i][1]), "=r"(a[i][2]), "=r"(a[i][3]) : "r"(addr));
            }
#pragma unroll
            for (int jj = 0; jj < 3; ++jj) {
                int nr = jj * 16 + ((lane >> 4) << 3) + (lane & 7);
                int ko = ks * 16 + ((lane >> 3) & 1) * 8;
                uint32_t addr = xb_u + (uint32_t)((nr * 72 + ko) * 2);
                asm volatile("ldmatrix.sync.aligned.m8n8.x4.shared.b16 {%0,%1,%2,%3}, [%4];"
                    : "=r"(b[jj][0]), "=r"(b[jj][1]), "=r"(b[jj][2]), "=r"(b[jj][3]) : "r"(addr));
            }
#pragma unroll
            for (int i = 0; i < 3; ++i)
#pragma unroll
                for (int jj = 0; jj < 3; ++jj) {
                    asm volatile(
                        "mma.sync.aligned.m16n8k16.row.col.f16.f16.f16.f16 "
                        "{%0,%1}, {%2,%3,%4,%5}, {%6,%7}, {%0,%1};"
                        : "+r"(acc[i][2 * jj][0]), "+r"(acc[i][2 * jj][1])
                        : "r"(a[i][0]), "r"(a[i][1]), "r"(a[i][2]), "r"(a[i][3]),
                          "r"(b[jj][0]), "r"(b[jj][1]));
                    asm volatile(
                        "mma.sync.aligned.m16n8k16.row.col.f16.f16.f16.f16 "
                        "{%0,%1}, {%2,%3,%4,%5}, {%6,%7}, {%0,%1};"
                        : "+r"(acc[i][2 * jj + 1][0]), "+r"(acc[i][2 * jj + 1][1])
                        : "r"(a[i][0]), "r"(a[i][1]), "r"(a[i][2]), "r"(a[i][3]),
                          "r"(b[jj][2]), "r"(b[jj][3]));
                }
        }
    }

    // register softmax; exp in-place (acc -> fp16 P)
    float sinv0[3], sinv1[3];
#pragma unroll
    for (int i = 0; i < 3; ++i) {
        float mx0 = -1e30f, mx1 = -1e30f;
#pragma unroll
        for (int j = 0; j < 6; ++j) {
            int c0 = j * 8 + t4 * 2;
            float2 f0 = __half22float2(*(__half2*)&acc[i][j][0]);
            float2 f1 = __half22float2(*(__half2*)&acc[i][j][1]);
            if (c0 < 41) { mx0 = fmaxf(mx0, f0.x); mx1 = fmaxf(mx1, f1.x); }
            if (c0 + 1 < 41) { mx0 = fmaxf(mx0, f0.y); mx1 = fmaxf(mx1, f1.y); }
        }
        mx0 = fmaxf(mx0, __shfl_xor_sync(0xffffffffu, mx0, 1));
        mx0 = fmaxf(mx0, __shfl_xor_sync(0xffffffffu, mx0, 2));
        mx1 = fmaxf(mx1, __shfl_xor_sync(0xffffffffu, mx1, 1));
        mx1 = fmaxf(mx1, __shfl_xor_sync(0xffffffffu, mx1, 2));
        float s0 = 0.f, s1 = 0.f;
#pragma unroll
        for (int j = 0; j < 6; ++j) {
            int c0 = j * 8 + t4 * 2;
            float2 f0 = __half22float2(*(__half2*)&acc[i][j][0]);
            float2 f1 = __half22float2(*(__half2*)&acc[i][j][1]);
            float e00 = (c0 < 41) ? __expf((f0.x - mx0) * SCALE_F) : 0.f;
            float e01 = (c0 + 1 < 41) ? __expf((f0.y - mx0) * SCALE_F) : 0.f;
            float e10 = (c0 < 41) ? __expf((f1.x - mx1) * SCALE_F) : 0.f;
            float e11 = (c0 + 1 < 41) ? __expf((f1.y - mx1) * SCALE_F) : 0.f;
            s0 += e00 + e01; s1 += e10 + e11;
            __half2 h0 = __floats2half2_rn(e00, e01);
            __half2 h1 = __floats2half2_rn(e10, e11);
            acc[i][j][0] = *(uint32_t*)&h0;
            acc[i][j][1] = *(uint32_t*)&h1;
        }
        s0 += __shfl_xor_sync(0xffffffffu, s0, 1);
        s0 += __shfl_xor_sync(0xffffffffu, s0, 2);
        s1 += __shfl_xor_sync(0xffffffffu, s1, 1);
        s1 += __shfl_xor_sync(0xffffffffu, s1, 2);
        sinv0[i] = 1.f / s0;
        sinv1[i] = 1.f / s1;
    }

    __syncwarp();

    float oa[3][2][4];
#pragma unroll
    for (int i = 0; i < 3; ++i)
#pragma unroll
        for (int j = 0; j < 2; ++j)
#pragma unroll
            for (int e = 0; e < 4; ++e) oa[i][j][e] = 0.f;
#pragma unroll
    for (int kt = 0; kt < 3; ++kt) {
        uint32_t bf[4];
        int nr = ((lane >> 4) << 3) + (lane & 7);
        int ko = kt * 16 + ((lane >> 3) & 1) * 8;
        uint32_t addr = xvT_u + (uint32_t)((nr * 56 + ko) * 2);
        asm volatile("ldmatrix.sync.aligned.m8n8.x4.shared.b16 {%0,%1,%2,%3}, [%4];"
            : "=r"(bf[0]), "=r"(bf[1]), "=r"(bf[2]), "=r"(bf[3]) : "r"(addr));
#pragma unroll
        for (int i = 0; i < 3; ++i) {
            asm volatile(
                "mma.sync.aligned.m16n8k16.row.col.f32.f16.f16.f32 "
                "{%0,%1,%2,%3}, {%4,%5,%6,%7}, {%8,%9}, {%0,%1,%2,%3};"
                : "+f"(oa[i][0][0]), "+f"(oa[i][0][1]), "+f"(oa[i][0][2]), "+f"(oa[i][0][3])
                : "r"(acc[i][2 * kt][0]), "r"(acc[i][2 * kt][1]),
                  "r"(acc[i][2 * kt + 1][0]), "r"(acc[i][2 * kt + 1][1]),
                  "r"(bf[0]), "r"(bf[1]));
            asm volatile(
                "mma.sync.aligned.m16n8k16.row.col.f32.f16.f16.f32 "
                "{%0,%1,%2,%3}, {%4,%5,%6,%7}, {%8,%9}, {%0,%1,%2,%3};"
                : "+f"(oa[i][1][0]), "+f"(oa[i][1][1]), "+f"(oa[i][1][2]), "+f"(oa[i][1][3])
                : "r"(acc[i][2 * kt][0]), "r"(acc[i][2 * kt][1]),
                  "r"(acc[i][2 * kt + 1][0]), "r"(acc[i][2 * kt + 1][1]),
                  "r"(bf[2]), "r"(bf[3]));
        }
    }
#pragma unroll
    for (int i = 0; i < 3; ++i) {
#pragma unroll
        for (int j = 0; j < 2; ++j) {
            int c0 = j * 8 + t4 * 2;
            int tA = i * 16 + gid;
            if (tA < 41) {
                float v0 = oa[i][j][0] * sinv0[i];
                float v1 = oa[i][j][1] * sinv0[i];
                __half2 pp = __floats2half2_rn(v0, v1);
                *(uint32_t*)(g_valb + ((size_t)n * 41 + tA) * 256 + h * 16 + c0) =
                    *(uint32_t*)&pp;
            }
            int tB = tA + 8;
            if (tB < 41) {
                float v0 = oa[i][j][2] * sinv1[i];
                float v1 = oa[i][j][3] * sinv1[i];
                __half2 pp = __floats2half2_rn(v0, v1);
                *(uint32_t*)(g_valb + ((size_t)n * 41 + tB) * 256 + h * 16 + c0) =
                    *(uint32_t*)&pp;
            }
        }
    }
}

// -------- kernel 5: word attention per sequence --------
__global__ void __launch_bounds__(256) word_kernel() {
    __shared__ float sl[41];
    int n = blockIdx.x;
    int tid = threadIdx.x;
    if (tid < 41) {
        const float4* sp = (const float4*)(g_spart + (size_t)(n * 41 + tid) * 8);
        float4 a = sp[0], b = sp[1];
        sl[tid] = ((a.x + a.y) + (a.z + a.w) + (b.x + b.y) + (b.z + b.w)) * SCALE_F;
    }
    __syncthreads();
    if (tid < 32) {
        float v0 = (tid < 41) ? sl[tid] : -1e30f;
        float v1 = (tid + 32 < 41) ? sl[tid + 32] : -1e30f;
        float m = fmaxf(v0, v1);
#pragma unroll
        for (int o = 16; o; o >>= 1) m = fmaxf(m, __shfl_xor_sync(0xffffffffu, m, o));
        float e0 = (tid < 41) ? expf(v0 - m) : 0.f;
        float e1 = (tid + 32 < 41) ? expf(v1 - m) : 0.f;
        float s = e0 + e1;
#pragma unroll
        for (int o = 16; o; o >>= 1) s += __shfl_xor_sync(0xffffffffu, s, o);
        float inv = 1.f / s;
        if (tid < 41) sl[tid] = e0 * inv;
        if (tid + 32 < 41) sl[tid + 32] = e1 * inv;
    }
    __syncthreads();
    float acc = 0.f;
    const half* vr = g_valb + (size_t)n * 41 * 256 + tid;
#pragma unroll 8
    for (int t = 0; t < 41; ++t)
        acc = fmaf(sl[t], __half2float(vr[(size_t)t * 256]), acc);
    g_rep[(size_t)n * 256 + tid] = acc;
}

// -------- kernel 6: mean over HIS, rank score, log-softmax over CDD --------
__global__ void __launch_bounds__(256) final_kernel(const float* __restrict__ Wl,
                                                    const float* __restrict__ blp,
                                                    float* __restrict__ out) {
    __shared__ float red[8];
    __shared__ float sc[5];
    int b = blockIdx.x;
    int tid = threadIdx.x;
    float wl = Wl[tid];
    for (int c = 0; c < 5; ++c) {
        const float* rp = g_rep + ((size_t)(b * 5 + c) * 50) * 256 + tid;
        float s = 0.f;
        for (int h = 0; h < 50; ++h) s += rp[(size_t)h * 256];
        s *= wl;
#pragma unroll
        for (int o = 16; o; o >>= 1) s += __shfl_xor_sync(0xffffffffu, s, o);
        if ((tid & 31) == 0) red[tid >> 5] = s;
        __syncthreads();
        if (tid < 8) {
            float v = red[tid];
#pragma unroll
            for (int o = 4; o; o >>= 1) v += __shfl_xor_sync(0xffu, v, o, 8);
            if (tid == 0) sc[c] = v * (1.f / 50.f) + blp[0];
        }
        __syncthreads();
    }
    if (tid == 0) {
        float m = sc[0];
        for (int c = 1; c < 5; ++c) m = fmaxf(m, sc[c]);
        float s = 0.f;
        for (int c = 0; c < 5; ++c) s += expf(sc[c] - m);
        float ls = logf(s);
        for (int c = 0; c < 5; ++c) out[b * 5 + c] = sc[c] - m - ls;
    }
}

// -------- host launcher --------
extern "C" void kernel_launch(void* const* d_in, const int* in_sizes, int n_in,
                              void* d_out, int out_size) {
    const int* cand = (const int*)d_in[0];
    const int* clk = (const int*)d_in[1];
    const float* emb = (const float*)d_in[2];
    const float* conv_w = (const float*)d_in[3];
    const float* conv_b = (const float*)d_in[4];
    const float* Wq = (const float*)d_in[5];
    const float* bq = (const float*)d_in[6];
    const float* Wv = (const float*)d_in[7];
    const float* bv = (const float*)d_in[8];
    const float* Wk = (const float*)d_in[9];
    const float* bk = (const float*)d_in[10];
    const float* qw = (const float*)d_in[11];
    const float* Wl = (const float*)d_in[12];
    const float* bl = (const float*)d_in[13];
    float* out = (float*)d_out;

    cudaFuncSetAttribute(attn_kernel, cudaFuncAttributeMaxDynamicSharedMemorySize,
                         ATTN_SMEM_BYTES);

    static const half* h_xub = nullptr;
    static const half* h_WcatTb = nullptr;
    static const half* h_WkTb = nullptr;
    static const half* h_valb = nullptr;
    static const float* h_bcat = nullptr;
    if (!h_xub) {
        void* p;
        cudaGetSymbolAddress(&p, g_xub);    h_xub = (const half*)p;
        cudaGetSymbolAddress(&p, g_WcatTb); h_WcatTb = (const half*)p;
        cudaGetSymbolAddress(&p, g_WkTb);   h_WkTb = (const half*)p;
        cudaGetSymbolAddress(&p, g_valb);   h_valb = (const half*)p;
        cudaGetSymbolAddress(&p, g_bcat);   h_bcat = (const float*)p;
    }

    prep_kernel<<<4352, 256>>>(Wq, bq, Wv, bv, Wk, conv_w);
    conv_mma_kernel<<<dim3(2, 169), 256>>>(cand, clk, emb, conv_b);
    gemm_mma_kernel<0><<<dim3(34, (NUROWS + 127) / 128), 256>>>(h_xub, h_WcatTb, h_bcat,
                                                                nullptr, NUROWS, 4352);
    attn_kernel<<<dim3(2, NSEQ), 256, ATTN_SMEM_BYTES>>>();
    gemm_mma_kernel<1><<<dim3(2, (MVAL + 127) / 128), 256>>>(h_valb, h_WkTb, bk,
                                                             qw, MVAL, NQD);
    word_kernel<<<NSEQ, 256>>>();
    final_kernel<<<NB, 256>>>(Wl, bl, out);
}

// round 17
// speedup vs baseline: 1.0453x; 1.0453x over previous
#include <cuda_runtime.h>
#include <cuda_bf16.h>
#include <cuda_fp16.h>
#include <math.h>
#include <stdint.h>

#define NB 16
#define NCDD 5
#define NHIS 50
#define NS 20
#define NT 41
#define NE 300
#define NF 256
#define NH 16
#define NDV 16
#define NQD 200
#define NSEQ 4000
#define NUROWS 21600
#define MID_BASE 17600
#define MVAL 164000
#define SCALE_F 0.057735026918962576f
#define CONV_K 928

#define CP_ASYNC16(dst, src) \
    asm volatile("cp.async.cg.shared.global [%0], [%1], 16;" :: "r"(dst), "l"(src))
#define CP_COMMIT() asm volatile("cp.async.commit_group;" ::: "memory")
#define CP_WAIT0() asm volatile("cp.async.wait_group 0;" ::: "memory")

// -------- static device scratch (no allocations) --------
__device__ half g_xub[NUROWS * NF];
__device__ half g_WcatTb[4352 * 256];
__device__ float g_bcat[4352];
__device__ half g_WkTb[200 * 256];
__device__ half g_cwb[256 * CONV_K];
__device__ half g_qb[(size_t)NUROWS * 4096];
__device__ float g_xv[(size_t)NUROWS * 256];
__device__ half g_valb[(size_t)MVAL * NF];
__device__ float g_spart[(size_t)MVAL * 4];
__device__ float g_rep[(size_t)NSEQ * NF];

// -------- kernel 0: pack transposed fp16 weights + bias --------
__global__ void prep_kernel(const float* __restrict__ Wq, const float* __restrict__ bq,
                            const float* __restrict__ Wv, const float* __restrict__ bv,
                            const float* __restrict__ Wk, const float* __restrict__ cw) {
    int idx = blockIdx.x * 256 + threadIdx.x;
    if (idx < 4352 * 256) {
        int nn = idx >> 8, k = idx & 255;
        float w;
        if (nn < 4096) {
            int h = nn >> 8, g = nn & 255;
            w = Wq[(h * 256 + k) * 256 + g];
        } else {
            int jj = nn - 4096;
            int h = jj >> 4, d = jj & 15;
            w = Wv[(h * 256 + k) * 16 + d];
        }
        g_WcatTb[idx] = __float2half(w);
    }
    if (idx < 200 * 256) {
        int nn = idx >> 8, k = idx & 255;
        g_WkTb[idx] = __float2half(Wk[k * 200 + nn]);
    }
    if (idx < 256 * CONV_K) {
        int f = idx / CONV_K, k = idx - f * CONV_K;
        g_cwb[idx] = __float2half(k < 900 ? cw[k * 256 + f] : 0.f);
    }
    if (idx < 4352) {
        if (idx < 4096) {
            int h = idx >> 8, g = idx & 255;
            g_bcat[idx] = bq[h * 256 + g];
        } else {
            g_bcat[idx] = bv[idx - 4096]; // bv folds through softmax (rows sum to 1)
        }
    }
}

// -------- kernel 1: conv as fp16 mma GEMM over im2col rows (fp32 acc) --------
__global__ void __launch_bounds__(256, 2) conv_mma_kernel(const int* __restrict__ cand,
                                                          const int* __restrict__ clk,
                                                          const float* __restrict__ emb,
                                                          const float* __restrict__ cb) {
    __shared__ half As[128 * 40];
    __shared__ half Bs[128 * 40];
    __shared__ int st[128][3];
    int tid = threadIdx.x;
    int w = tid >> 5, lane = tid & 31;
    int wm = w >> 2, wn = w & 3;
    int m0 = blockIdx.y * 128;
    int n0 = blockIdx.x * 128;

    if (tid < 128) {
        int row = m0 + tid;
        int t0 = -1, t1 = -1, t2 = -1;
        if (row < NUROWS) {
            if (row < 1600) {
                int bc = row / 20, t = row - bc * 20;
                const int* ct = cand + bc * 20;
                t0 = (t - 1 >= 0) ? ct[t - 1] : -1;
                t1 = ct[t];
                t2 = (t + 1 < 20) ? ct[t + 1] : 1;
            } else if (row < MID_BASE) {
                int r2 = row - 1600;
                int bh = r2 / 20, tt = r2 - bh * 20;
                const int* ht = clk + bh * 20;
                t0 = (tt == 0) ? 1 : ht[tt - 1];
                t1 = ht[tt];
                t2 = (tt + 1 < 20) ? ht[tt + 1] : -1;
            } else {
                int nn = row - MID_BASE;
                int b = nn / 250, rr = nn - b * 250;
                int c = rr / 50, hh = rr - c * 50;
                t0 = cand[(b * 5 + c) * 20 + 19];
                t1 = 1;
                t2 = clk[(b * 50 + hh) * 20 + 0];
            }
        }
        st[tid][0] = t0; st[tid][1] = t1; st[tid][2] = t2;
    }

    uint32_t As_u = (uint32_t)__cvta_generic_to_shared(As);
    uint32_t Bs_u = (uint32_t)__cvta_generic_to_shared(Bs);

    float acc[4][4][4];
#pragma unroll
    for (int i = 0; i < 4; ++i)
#pragma unroll
        for (int j = 0; j < 4; ++j)
#pragma unroll
            for (int e = 0; e < 4; ++e) acc[i][j][e] = 0.f;

    for (int kc = 0; kc < CONV_K; kc += 32) {
        __syncthreads();
#pragma unroll
        for (int j = 0; j < 4; ++j) {
            int i = tid + j * 256;
            int r = i >> 3, q = i & 7;
            int k0 = kc + q * 4;
            uint2 u = make_uint2(0, 0);
            if (k0 < 900) {
                int tap = k0 / 300;
                int e0 = k0 - tap * 300;
                int tok = st[r][tap];
                if (tok >= 0) {
                    float4 v = *(const float4*)(emb + (size_t)tok * 300 + e0);
                    __half2 p0 = __floats2half2_rn(v.x, v.y);
                    __half2 p1 = __floats2half2_rn(v.z, v.w);
                    u.x = *(uint32_t*)&p0;
                    u.y = *(uint32_t*)&p1;
                }
            }
            *(uint2*)(As + r * 40 + q * 4) = u;
        }
#pragma unroll
        for (int j = 0; j < 2; ++j) {
            int i = tid + j * 256;
            int r = i >> 2, kq = i & 3;
            *(uint4*)(Bs + r * 40 + kq * 8) =
                *(const uint4*)(g_cwb + (size_t)(n0 + r) * CONV_K + kc + kq * 8);
        }
        __syncthreads();
#pragma unroll
        for (int ks = 0; ks < 2; ++ks) {
            uint32_t a[4][4], b[4][2];
#pragma unroll
            for (int i = 0; i < 4; ++i) {
                uint32_t addr = As_u +
                    (uint32_t)(((wm * 64 + i * 16 + (lane & 15)) * 40 + ks * 16 + (lane >> 4) * 8) * 2);
                asm volatile("ldmatrix.sync.aligned.m8n8.x4.shared.b16 {%0,%1,%2,%3}, [%4];"
                    : "=r"(a[i][0]), "=r"(a[i][1]), "=r"(a[i][2]), "=r"(a[i][3]) : "r"(addr));
            }
#pragma unroll
            for (int j = 0; j < 4; ++j) {
                int nr = wn * 32 + j * 8 + (lane & 7);
                uint32_t addr = Bs_u +
                    (uint32_t)((nr * 40 + ks * 16 + ((lane >> 3) & 1) * 8) * 2);
                asm volatile("ldmatrix.sync.aligned.m8n8.x2.shared.b16 {%0,%1}, [%2];"
                    : "=r"(b[j][0]), "=r"(b[j][1]) : "r"(addr));
            }
#pragma unroll
            for (int i = 0; i < 4; ++i)
#pragma unroll
                for (int j = 0; j < 4; ++j)
                    asm volatile(
                        "mma.sync.aligned.m16n8k16.row.col.f32.f16.f16.f32 "
                        "{%0,%1,%2,%3}, {%4,%5,%6,%7}, {%8,%9}, {%0,%1,%2,%3};"
                        : "+f"(acc[i][j][0]), "+f"(acc[i][j][1]),
                          "+f"(acc[i][j][2]), "+f"(acc[i][j][3])
                        : "r"(a[i][0]), "r"(a[i][1]), "r"(a[i][2]), "r"(a[i][3]),
                          "r"(b[j][0]), "r"(b[j][1]));
        }
    }

    int gid = lane >> 2;
#pragma unroll
    for (int i = 0; i < 4; ++i) {
#pragma unroll
        for (int j = 0; j < 4; ++j) {
            int c0 = n0 + wn * 32 + j * 8 + (lane & 3) * 2;
            float b0 = cb[c0], b1 = cb[c0 + 1];
#pragma unroll
            for (int hf = 0; hf < 2; ++hf) {
                int m = m0 + wm * 64 + i * 16 + gid + hf * 8;
                if (m >= NUROWS) continue;
                float v0 = fmaxf(acc[i][j][hf * 2 + 0] + b0, 0.f);
                float v1 = fmaxf(acc[i][j][hf * 2 + 1] + b1, 0.f);
                __half2 p = __floats2half2_rn(v0, v1);
                *(uint32_t*)(g_xub + (size_t)m * 256 + c0) = *(uint32_t*)&p;
            }
        }
    }
}

// -------- fp16 tensor-core GEMM, 128x256 tile (fp16 acc), K=256, double-buffered ----
// MODE 0: n<4096 -> g_qb fp16; n>=4096 -> g_xv fp32.
// MODE 1: fused word-k partials -> g_spart (4 per row).
template <int MODE>
__global__ void __launch_bounds__(256, 2) gemm_mma_kernel(const half* __restrict__ Ag,
                                                          const half* __restrict__ Bt,
                                                          const float* __restrict__ bias,
                                                          const float* __restrict__ qw,
                                                          int M, int N) {
    __shared__ half As[128 * 56];
    __shared__ half Bs[256 * 56];
    __shared__ float qws[200];
    int tid = threadIdx.x;
    int w = tid >> 5, lane = tid & 31;
    int wm = w >> 2, wn = w & 3;         // warp tile: 64m x 64n
    int m0 = blockIdx.y * 128;
    int n0 = blockIdx.x * 256;

    if (MODE == 1 && tid < 200) qws[tid] = qw[tid];

    uint32_t As_u = (uint32_t)__cvta_generic_to_shared(As);
    uint32_t Bs_u = (uint32_t)__cvta_generic_to_shared(Bs);

    // fp16 accumulators: [i][j][0]={rows gid}, [1]={rows gid+8}
    uint32_t acc[4][8][2];
#pragma unroll
    for (int i = 0; i < 4; ++i)
#pragma unroll
        for (int j = 0; j < 8; ++j) { acc[i][j][0] = 0u; acc[i][j][1] = 0u; }

    uint4 pre[6];
#pragma unroll
    for (int j = 0; j < 6; ++j) {
        int i = tid + j * 256;           // 0..1535 = 384 rows x 4 chunks
        int r = i >> 2;
        int kq = i & 3;
        uint4 v = make_uint4(0, 0, 0, 0);
        if (r < 128) {
            int m = m0 + r;
            if (m < M) v = *(const uint4*)(Ag + (size_t)m * 256 + kq * 8);
        } else {
            int nn = n0 + (r - 128);
            if (nn < N) v = *(const uint4*)(Bt + (size_t)nn * 256 + kq * 8);
        }
        pre[j] = v;
    }

    for (int kc = 0; kc < 256; kc += 32) {
        __syncthreads();
#pragma unroll
        for (int j = 0; j < 6; ++j) {
            int i = tid + j * 256;
            int r = i >> 2;
            int kq = i & 3;
            if (r < 128) *(uint4*)(As + r * 56 + kq * 8) = pre[j];
            else         *(uint4*)(Bs + (r - 128) * 56 + kq * 8) = pre[j];
        }
        __syncthreads();
        if (kc + 32 < 256) {
            int kn = kc + 32;
#pragma unroll
            for (int j = 0; j < 6; ++j) {
                int i = tid + j * 256;
                int r = i >> 2;
                int kq = i & 3;
                uint4 v = make_uint4(0, 0, 0, 0);
                if (r < 128) {
                    int m = m0 + r;
                    if (m < M) v = *(const uint4*)(Ag + (size_t)m * 256 + kn + kq * 8);
                } else {
                    int nn = n0 + (r - 128);
                    if (nn < N) v = *(const uint4*)(Bt + (size_t)nn * 256 + kn + kq * 8);
                }
                pre[j] = v;
            }
        }
#pragma unroll
        for (int ks = 0; ks < 2; ++ks) {
            uint32_t a[4][4], b[4][4];
#pragma unroll
            for (int i = 0; i < 4; ++i) {
                uint32_t addr = As_u +
                    (uint32_t)(((wm * 64 + i * 16 + (lane & 15)) * 56 + ks * 16 + (lane >> 4) * 8) * 2);
                asm volatile("ldmatrix.sync.aligned.m8n8.x4.shared.b16 {%0,%1,%2,%3}, [%4];"
                    : "=r"(a[i][0]), "=r"(a[i][1]), "=r"(a[i][2]), "=r"(a[i][3]) : "r"(addr));
            }
#pragma unroll
            for (int jj = 0; jj < 4; ++jj) {
                // x4 pair: n-tiles 2jj, 2jj+1 (16 B rows)
                int nr = wn * 64 + jj * 16 + ((lane >> 4) << 3) + (lane & 7);
                uint32_t addr = Bs_u +
                    (uint32_t)((nr * 56 + ks * 16 + ((lane >> 3) & 1) * 8) * 2);
                asm volatile("ldmatrix.sync.aligned.m8n8.x4.shared.b16 {%0,%1,%2,%3}, [%4];"
                    : "=r"(b[jj][0]), "=r"(b[jj][1]), "=r"(b[jj][2]), "=r"(b[jj][3]) : "r"(addr));
            }
#pragma unroll
            for (int i = 0; i < 4; ++i)
#pragma unroll
                for (int jj = 0; jj < 4; ++jj) {
                    asm volatile(
                        "mma.sync.aligned.m16n8k16.row.col.f16.f16.f16.f16 "
                        "{%0,%1}, {%2,%3,%4,%5}, {%6,%7}, {%0,%1};"
                        : "+r"(acc[i][2 * jj][0]), "+r"(acc[i][2 * jj][1])
                        : "r"(a[i][0]), "r"(a[i][1]), "r"(a[i][2]), "r"(a[i][3]),
                          "r"(b[jj][0]), "r"(b[jj][1]));
                    asm volatile(
                        "mma.sync.aligned.m16n8k16.row.col.f16.f16.f16.f16 "
                        "{%0,%1}, {%2,%3,%4,%5}, {%6,%7}, {%0,%1};"
                        : "+r"(acc[i][2 * jj + 1][0]), "+r"(acc[i][2 * jj + 1][1])
                        : "r"(a[i][0]), "r"(a[i][1]), "r"(a[i][2]), "r"(a[i][3]),
                          "r"(b[jj][2]), "r"(b[jj][3]));
                }
        }
    }

    int gid = lane >> 2;
    if (MODE == 0) {
#pragma unroll
        for (int i = 0; i < 4; ++i) {
#pragma unroll
            for (int j = 0; j < 8; ++j) {
                int c0 = n0 + wn * 64 + j * 8 + (lane & 3) * 2;
                float b0 = bias[c0], b1 = bias[c0 + 1];
                float2 f0 = __half22float2(*(__half2*)&acc[i][j][0]);
                float2 f1 = __half22float2(*(__half2*)&acc[i][j][1]);
#pragma unroll
                for (int hf = 0; hf < 2; ++hf) {
                    int m = m0 + wm * 64 + i * 16 + gid + hf * 8;
                    if (m >= M) continue;
                    float v0 = (hf ? f1.x : f0.x) + b0;
                    float v1 = (hf ? f1.y : f0.y) + b1;
                    if (c0 < 4096) {
                        __half2 p = __floats2half2_rn(v0, v1);
                        *(uint32_t*)(g_qb + (size_t)m * 4096 + c0) = *(uint32_t*)&p;
                    } else {
                        *(float2*)(g_xv + (size_t)m * 256 + (c0 - 4096)) =
                            make_float2(v0, v1);
                    }
                }
            }
        }
    } else {
        int t4 = lane & 3;
#pragma unroll
        for (int hf = 0; hf < 2; ++hf) {
#pragma unroll
            for (int i = 0; i < 4; ++i) {
                int m = m0 + wm * 64 + i * 16 + gid + hf * 8;
                float part = 0.f;
#pragma unroll
                for (int j = 0; j < 8; ++j) {
                    int c0 = n0 + wn * 64 + j * 8 + t4 * 2;
                    float2 f = __half22float2(*(__half2*)&acc[i][j][hf]);
                    if (c0 < N)
                        part += tanhf(f.x + bias[c0]) * qws[c0];
                    if (c0 + 1 < N)
                        part += tanhf(f.y + bias[c0 + 1]) * qws[c0 + 1];
                }
                part += __shfl_xor_sync(0xffffffffu, part, 1);
                part += __shfl_xor_sync(0xffffffffu, part, 2);
                if (t4 == 0 && m < M)
                    g_spart[(size_t)m * 4 + wn] = part;
            }
        }
    }
}

// -------- kernel 3: attention; 1 warp = 1 head, fp16-acc scores, in-place softmax --------
// smem: xb 48*72*2=6912 | qbA 8x6912=55296 | xvTA 8x1792=14336  => 76544 B
#define ATTN_SMEM_BYTES 76544

__global__ void __launch_bounds__(256, 3) attn_kernel() {
    extern __shared__ char smc[];
    half* xb = (half*)smc;
    half* qbA = (half*)(smc + 6912);
    half* xvTA = (half*)(smc + 6912 + 55296);
    __shared__ int rows[41];

    int n = blockIdx.y;
    int hb = blockIdx.x;
    int tid = threadIdx.x;
    int w = tid >> 5;
    int lane = tid & 31;
    int h = hb * 8 + w;
    int t4 = lane & 3;
    int gid = lane >> 2;

    half* qb = qbA + w * 3456;
    half* xvT = xvTA + w * 896;

    uint32_t xb_u = (uint32_t)__cvta_generic_to_shared(xb);
    uint32_t qb_u = (uint32_t)__cvta_generic_to_shared(qb);
    uint32_t xvT_u = (uint32_t)__cvta_generic_to_shared(xvT);

    // hoisted per-lane ldmatrix bases
    uint32_t qA_base = qb_u + (uint32_t)(((lane & 15) * 72 + (lane >> 4) * 8) * 2);
    uint32_t xB_base = xb_u +
        (uint32_t)(((((lane >> 4) << 3) + (lane & 7)) * 72 + ((lane >> 3) & 1) * 8) * 2);
    uint32_t vB_base = xvT_u +
        (uint32_t)(((((lane >> 4) << 3) + (lane & 7)) * 56 + ((lane >> 3) & 1) * 8) * 2);

    if (tid < 41) {
        int b = n / 250, rr = n - b * 250;
        int c = rr / 50, hh = rr - c * 50;
        int t = tid, r;
        if (t < 20)       r = (b * 5 + c) * 20 + t;
        else if (t == 20) r = MID_BASE + n;
        else              r = 1600 + (b * 50 + hh) * 20 + (t - 21);
        rows[t] = r;
    }
    __syncthreads();

    for (int i = lane; i < 240; i += 32) {
        int d = i / 15, s = 41 + i % 15;
        xvT[d * 56 + s] = __float2half(0.f);
    }
    for (int i = lane; i < 164; i += 32) {
        int s = i >> 2, dq = (i & 3) * 4;
        float4 v = *(const float4*)(g_xv + (size_t)rows[s] * 256 + h * 16 + dq);
        xvT[(dq + 0) * 56 + s] = __float2half(v.x);
        xvT[(dq + 1) * 56 + s] = __float2half(v.y);
        xvT[(dq + 2) * 56 + s] = __float2half(v.z);
        xvT[(dq + 3) * 56 + s] = __float2half(v.w);
    }

    uint32_t acc[3][6][2];
#pragma unroll
    for (int i = 0; i < 3; ++i)
#pragma unroll
        for (int j = 0; j < 6; ++j) { acc[i][j][0] = 0u; acc[i][j][1] = 0u; }

    for (int kc = 0; kc < 256; kc += 64) {
        __syncthreads();
        for (int i = tid; i < 328; i += 256) {
            int t = i >> 3, kq = i & 7;
            CP_ASYNC16(xb_u + (uint32_t)(t * 144 + kq * 16),
                       g_xub + (size_t)rows[t] * 256 + kc + kq * 8);
        }
        for (int i = lane; i < 328; i += 32) {
            int t = i >> 3, kq = i & 7;
            CP_ASYNC16(qb_u + (uint32_t)(t * 144 + kq * 16),
                       g_qb + (size_t)rows[t] * 4096 + h * 256 + kc + kq * 8);
        }
        CP_COMMIT();
        CP_WAIT0();
        __syncthreads();
#pragma unroll
        for (int ks = 0; ks < 4; ++ks) {
            uint32_t a[3][4], b[3][4];
#pragma unroll
            for (int i = 0; i < 3; ++i) {
                uint32_t addr = qA_base + (uint32_t)(i * 2304 + ks * 32);
                asm volatile("ldmatrix.sync.aligned.m8n8.x4.shared.b16 {%0,%1,%2,%3}, [%4];"
                    : "=r"(a[i][0]), "=r"(a[i][1]), "=r"(a[i][2]), "=r"(a[i][3]) : "r"(addr));
            }
#pragma unroll
            for (int jj = 0; jj < 3; ++jj) {
                uint32_t addr = xB_base + (uint32_t)(jj * 2304 + ks * 32);
                asm volatile("ldmatrix.sync.aligned.m8n8.x4.shared.b16 {%0,%1,%2,%3}, [%4];"
                    : "=r"(b[jj][0]), "=r"(b[jj][1]), "=r"(b[jj][2]), "=r"(b[jj][3]) : "r"(addr));
            }
#pragma unroll
            for (int i = 0; i < 3; ++i)
#pragma unroll
                for (int jj = 0; jj < 3; ++jj) {
                    asm volatile(
                        "mma.sync.aligned.m16n8k16.row.col.f16.f16.f16.f16 "
                        "{%0,%1}, {%2,%3,%4,%5}, {%6,%7}, {%0,%1};"
                        : "+r"(acc[i][2 * jj][0]), "+r"(acc[i][2 * jj][1])
                        : "r"(a[i][0]), "r"(a[i][1]), "r"(a[i][2]), "r"(a[i][3]),
                          "r"(b[jj][0]), "r"(b[jj][1]));
                    asm volatile(
                        "mma.sync.aligned.m16n8k16.row.col.f16.f16.f16.f16 "
                        "{%0,%1}, {%2,%3,%4,%5}, {%6,%7}, {%0,%1};"
                        : "+r"(acc[i][2 * jj + 1][0]), "+r"(acc[i][2 * jj + 1][1])
                        : "r"(a[i][0]), "r"(a[i][1]), "r"(a[i][2]), "r"(a[i][3]),
                          "r"(b[jj][2]), "r"(b[jj][3]));
                }
        }
    }

    // register softmax; exp in-place (acc -> fp16 P)
    float sinv0[3], sinv1[3];
#pragma unroll
    for (int i = 0; i < 3; ++i) {
        float mx0 = -1e30f, mx1 = -1e30f;
#pragma unroll
        for (int j = 0; j < 6; ++j) {
            int c0 = j * 8 + t4 * 2;
            float2 f0 = __half22float2(*(__half2*)&acc[i][j][0]);
            float2 f1 = __half22float2(*(__half2*)&acc[i][j][1]);
            if (c0 < 41) { mx0 = fmaxf(mx0, f0.x); mx1 = fmaxf(mx1, f1.x); }
            if (c0 + 1 < 41) { mx0 = fmaxf(mx0, f0.y); mx1 = fmaxf(mx1, f1.y); }
        }
        mx0 = fmaxf(mx0, __shfl_xor_sync(0xffffffffu, mx0, 1));
        mx0 = fmaxf(mx0, __shfl_xor_sync(0xffffffffu, mx0, 2));
        mx1 = fmaxf(mx1, __shfl_xor_sync(0xffffffffu, mx1, 1));
        mx1 = fmaxf(mx1, __shfl_xor_sync(0xffffffffu, mx1, 2));
        float s0 = 0.f, s1 = 0.f;
#pragma unroll
        for (int j = 0; j < 6; ++j) {
            int c0 = j * 8 + t4 * 2;
            float2 f0 = __half22float2(*(__half2*)&acc[i][j][0]);
            float2 f1 = __half22float2(*(__half2*)&acc[i][j][1]);
            float e00 = (c0 < 41) ? __expf((f0.x - mx0) * SCALE_F) : 0.f;
            float e01 = (c0 + 1 < 41) ? __expf((f0.y - mx0) * SCALE_F) : 0.f;
            float e10 = (c0 < 41) ? __expf((f1.x - mx1) * SCALE_F) : 0.f;
            float e11 = (c0 + 1 < 41) ? __expf((f1.y - mx1) * SCALE_F) : 0.f;
            s0 += e00 + e01; s1 += e10 + e11;
            __half2 h0 = __floats2half2_rn(e00, e01);
            __half2 h1 = __floats2half2_rn(e10, e11);
            acc[i][j][0] = *(uint32_t*)&h0;
            acc[i][j][1] = *(uint32_t*)&h1;
        }
        s0 += __shfl_xor_sync(0xffffffffu, s0, 1);
        s0 += __shfl_xor_sync(0xffffffffu, s0, 2);
        s1 += __shfl_xor_sync(0xffffffffu, s1, 1);
        s1 += __shfl_xor_sync(0xffffffffu, s1, 2);
        sinv0[i] = 1.f / s0;
        sinv1[i] = 1.f / s1;
    }

    __syncwarp();

    float oa[3][2][4];
#pragma unroll
    for (int i = 0; i < 3; ++i)
#pragma unroll
        for (int j = 0; j < 2; ++j)
#pragma unroll
            for (int e = 0; e < 4; ++e) oa[i][j][e] = 0.f;
#pragma unroll
    for (int kt = 0; kt < 3; ++kt) {
        uint32_t bf[4];
        uint32_t addr = vB_base + (uint32_t)(kt * 32);
        asm volatile("ldmatrix.sync.aligned.m8n8.x4.shared.b16 {%0,%1,%2,%3}, [%4];"
            : "=r"(bf[0]), "=r"(bf[1]), "=r"(bf[2]), "=r"(bf[3]) : "r"(addr));
#pragma unroll
        for (int i = 0; i < 3; ++i) {
            asm volatile(
                "mma.sync.aligned.m16n8k16.row.col.f32.f16.f16.f32 "
                "{%0,%1,%2,%3}, {%4,%5,%6,%7}, {%8,%9}, {%0,%1,%2,%3};"
                : "+f"(oa[i][0][0]), "+f"(oa[i][0][1]), "+f"(oa[i][0][2]), "+f"(oa[i][0][3])
                : "r"(acc[i][2 * kt][0]), "r"(acc[i][2 * kt][1]),
                  "r"(acc[i][2 * kt + 1][0]), "r"(acc[i][2 * kt + 1][1]),
                  "r"(bf[0]), "r"(bf[1]));
            asm volatile(
                "mma.sync.aligned.m16n8k16.row.col.f32.f16.f16.f32 "
                "{%0,%1,%2,%3}, {%4,%5,%6,%7}, {%8,%9}, {%0,%1,%2,%3};"
                : "+f"(oa[i][1][0]), "+f"(oa[i][1][1]), "+f"(oa[i][1][2]), "+f"(oa[i][1][3])
                : "r"(acc[i][2 * kt][0]), "r"(acc[i][2 * kt][1]),
                  "r"(acc[i][2 * kt + 1][0]), "r"(acc[i][2 * kt + 1][1]),
                  "r"(bf[2]), "r"(bf[3]));
        }
    }
#pragma unroll
    for (int i = 0; i < 3; ++i) {
#pragma unroll
        for (int j = 0; j < 2; ++j) {
            int c0 = j * 8 + t4 * 2;
            int tA = i * 16 + gid;
            if (tA < 41) {
                float v0 = oa[i][j][0] * sinv0[i];
                float v1 = oa[i][j][1] * sinv0[i];
                __half2 pp = __floats2half2_rn(v0, v1);
                *(uint32_t*)(g_valb + ((size_t)n * 41 + tA) * 256 + h * 16 + c0) =
                    *(uint32_t*)&pp;
            }
            int tB = tA + 8;
            if (tB < 41) {
                float v0 = oa[i][j][2] * sinv1[i];
                float v1 = oa[i][j][3] * sinv1[i];
                __half2 pp = __floats2half2_rn(v0, v1);
                *(uint32_t*)(g_valb + ((size_t)n * 41 + tB) * 256 + h * 16 + c0) =
                    *(uint32_t*)&pp;
            }
        }
    }
}

// -------- kernel 5: word attention per sequence --------
__global__ void __launch_bounds__(256) word_kernel() {
    __shared__ float sl[41];
    int n = blockIdx.x;
    int tid = threadIdx.x;
    if (tid < 41) {
        float4 a = *(const float4*)(g_spart + (size_t)(n * 41 + tid) * 4);
        sl[tid] = ((a.x + a.y) + (a.z + a.w)) * SCALE_F;
    }
    __syncthreads();
    if (tid < 32) {
        float v0 = (tid < 41) ? sl[tid] : -1e30f;
        float v1 = (tid + 32 < 41) ? sl[tid + 32] : -1e30f;
        float m = fmaxf(v0, v1);
#pragma unroll
        for (int o = 16; o; o >>= 1) m = fmaxf(m, __shfl_xor_sync(0xffffffffu, m, o));
        float e0 = (tid < 41) ? expf(v0 - m) : 0.f;
        float e1 = (tid + 32 < 41) ? expf(v1 - m) : 0.f;
        float s = e0 + e1;
#pragma unroll
        for (int o = 16; o; o >>= 1) s += __shfl_xor_sync(0xffffffffu, s, o);
        float inv = 1.f / s;
        if (tid < 41) sl[tid] = e0 * inv;
        if (tid + 32 < 41) sl[tid + 32] = e1 * inv;
    }
    __syncthreads();
    float acc = 0.f;
    const half* vr = g_valb + (size_t)n * 41 * 256 + tid;
#pragma unroll 8
    for (int t = 0; t < 41; ++t)
        acc = fmaf(sl[t], __half2float(vr[(size_t)t * 256]), acc);
    g_rep[(size_t)n * 256 + tid] = acc;
}

// -------- kernel 6: mean over HIS, rank score, log-softmax over CDD --------
__global__ void __launch_bounds__(256) final_kernel(const float* __restrict__ Wl,
                                                    const float* __restrict__ blp,
                                                    float* __restrict__ out) {
    __shared__ float red[8];
    __shared__ float sc[5];
    int b = blockIdx.x;
    int tid = threadIdx.x;
    float wl = Wl[tid];
    for (int c = 0; c < 5; ++c) {
        const float* rp = g_rep + ((size_t)(b * 5 + c) * 50) * 256 + tid;
        float s = 0.f;
        for (int h = 0; h < 50; ++h) s += rp[(size_t)h * 256];
        s *= wl;
#pragma unroll
        for (int o = 16; o; o >>= 1) s += __shfl_xor_sync(0xffffffffu, s, o);
        if ((tid & 31) == 0) red[tid >> 5] = s;
        __syncthreads();
        if (tid < 8) {
            float v = red[tid];
#pragma unroll
            for (int o = 4; o; o >>= 1) v += __shfl_xor_sync(0xffu, v, o, 8);
            if (tid == 0) sc[c] = v * (1.f / 50.f) + blp[0];
        }
        __syncthreads();
    }
    if (tid == 0) {
        float m = sc[0];
        for (int c = 1; c < 5; ++c) m = fmaxf(m, sc[c]);
        float s = 0.f;
        for (int c = 0; c < 5; ++c) s += expf(sc[c] - m);
        float ls = logf(s);
        for (int c = 0; c < 5; ++c) out[b * 5 + c] = sc[c] - m - ls;
    }
}

// -------- host launcher --------
extern "C" void kernel_launch(void* const* d_in, const int* in_sizes, int n_in,
                              void* d_out, int out_size) {
    const int* cand = (const int*)d_in[0];
    const int* clk = (const int*)d_in[1];
    const float* emb = (const float*)d_in[2];
    const float* conv_w = (const float*)d_in[3];
    const float* conv_b = (const float*)d_in[4];
    const float* Wq = (const float*)d_in[5];
    const float* bq = (const float*)d_in[6];
    const float* Wv = (const float*)d_in[7];
    const float* bv = (const float*)d_in[8];
    const float* Wk = (const float*)d_in[9];
    const float* bk = (const float*)d_in[10];
    const float* qw = (const float*)d_in[11];
    const float* Wl = (const float*)d_in[12];
    const float* bl = (const float*)d_in[13];
    float* out = (float*)d_out;

    cudaFuncSetAttribute(attn_kernel, cudaFuncAttributeMaxDynamicSharedMemorySize,
                         ATTN_SMEM_BYTES);

    static const half* h_xub = nullptr;
    static const half* h_WcatTb = nullptr;
    static const half* h_WkTb = nullptr;
    static const half* h_valb = nullptr;
    static const float* h_bcat = nullptr;
    if (!h_xub) {
        void* p;
        cudaGetSymbolAddress(&p, g_xub);    h_xub = (const half*)p;
        cudaGetSymbolAddress(&p, g_WcatTb); h_WcatTb = (const half*)p;
        cudaGetSymbolAddress(&p, g_WkTb);   h_WkTb = (const half*)p;
        cudaGetSymbolAddress(&p, g_valb);   h_valb = (const half*)p;
        cudaGetSymbolAddress(&p, g_bcat);   h_bcat = (const float*)p;
    }

    prep_kernel<<<4352, 256>>>(Wq, bq, Wv, bv, Wk, conv_w);
    conv_mma_kernel<<<dim3(2, 169), 256>>>(cand, clk, emb, conv_b);
    gemm_mma_kernel<0><<<dim3(17, (NUROWS + 127) / 128), 256>>>(h_xub, h_WcatTb, h_bcat,
                                                                nullptr, NUROWS, 4352);
    attn_kernel<<<dim3(2, NSEQ), 256, ATTN_SMEM_BYTES>>>();
    gemm_mma_kernel<1><<<dim3(1, (MVAL + 127) / 128), 256>>>(h_valb, h_WkTb, bk,
                                                             qw, MVAL, NQD);
    word_kernel<<<NSEQ, 256>>>();
    final_kernel<<<NB, 256>>>(Wl, bl, out);
}